// round 2
// baseline (speedup 1.0000x reference)
#include <cuda_runtime.h>
#include <cstdint>

// ---------------- constants ----------------
#define BB 8
#define NN 8192
#define DD 512
#define HH 8
#define MM 64
// HD = 64, H*M = 512

// ---------------- device scratch (no allocs allowed) ----------------
__device__ float g_kv[67108864];        // [B,N,2D]  256MB
__device__ float g_scores[33554432];    // [B,512,N] 128MB
__device__ float g_mixed[33554432];     // [B,512,N] 128MB (becomes slice_w in place)
__device__ float g_sumw[4096];          // [B,512]
__device__ float g_part[4194304];       // [64 bh][16 splits][64*64]
__device__ float g_stok[262144];        // [B,H,M,HD]
__device__ float g_st[262144];          // [B,M,D]
__device__ float g_qkv[786432];         // [B*M, 1536]
__device__ float g_otok[262144];        // [B,H,M,HD]
__device__ float g_pre[33554432];       // [B,N,D] 128MB

// ---------------- generic tiled SGEMM: C = A[M,K] @ B[K,N] (+bias) ----------------
// 128x128 tile, BK=16, 256 threads, 8x8 per thread. All dims multiples of tile.
__global__ __launch_bounds__(256)
void sgemm_kernel(const float* __restrict__ A, const float* __restrict__ Bm,
                  const float* __restrict__ bias, float* __restrict__ C,
                  int Mdim, int Ndim, int Kdim,
                  long long Abs, long long Bbs, long long Cbs)
{
    const int bz = blockIdx.z;
    A  += bz * Abs;
    Bm += bz * Bbs;
    C  += bz * Cbs;

    __shared__ float Asm[16][128];
    __shared__ float Bsm[16][128];

    const int tid = threadIdx.x;
    const int tx = tid & 15, ty = tid >> 4;
    const int m0 = blockIdx.y * 128, n0 = blockIdx.x * 128;

    float acc[8][8];
#pragma unroll
    for (int i = 0; i < 8; i++)
#pragma unroll
        for (int j = 0; j < 8; j++) acc[i][j] = 0.f;

    for (int kt = 0; kt < Kdim; kt += 16) {
#pragma unroll
        for (int i = 0; i < 2; i++) {
            int idx = tid + i * 256;            // 0..511
            int r = idx >> 2;                   // 0..127
            int c4 = idx & 3;                   // 0..3
            float4 v = *(const float4*)&A[(long long)(m0 + r) * Kdim + kt + c4 * 4];
            Asm[c4 * 4 + 0][r] = v.x;
            Asm[c4 * 4 + 1][r] = v.y;
            Asm[c4 * 4 + 2][r] = v.z;
            Asm[c4 * 4 + 3][r] = v.w;
        }
#pragma unroll
        for (int i = 0; i < 2; i++) {
            int idx = tid + i * 256;
            int r = idx >> 5;                   // 0..15
            int c4 = idx & 31;                  // 0..31
            *(float4*)&Bsm[r][c4 * 4] =
                *(const float4*)&Bm[(long long)(kt + r) * Ndim + n0 + c4 * 4];
        }
        __syncthreads();
#pragma unroll
        for (int k = 0; k < 16; k++) {
            float4 a0 = *(float4*)&Asm[k][ty * 8];
            float4 a1 = *(float4*)&Asm[k][ty * 8 + 4];
            float4 b0 = *(float4*)&Bsm[k][tx * 8];
            float4 b1 = *(float4*)&Bsm[k][tx * 8 + 4];
            float ra[8] = {a0.x, a0.y, a0.z, a0.w, a1.x, a1.y, a1.z, a1.w};
            float rb[8] = {b0.x, b0.y, b0.z, b0.w, b1.x, b1.y, b1.z, b1.w};
#pragma unroll
            for (int i = 0; i < 8; i++)
#pragma unroll
                for (int j = 0; j < 8; j++) acc[i][j] += ra[i] * rb[j];
        }
        __syncthreads();
    }

#pragma unroll
    for (int i = 0; i < 8; i++) {
        long long row = m0 + ty * 8 + i;
#pragma unroll
        for (int j = 0; j < 8; j += 4) {
            int col = n0 + tx * 8 + j;
            float4 v;
            v.x = acc[i][j + 0]; v.y = acc[i][j + 1];
            v.z = acc[i][j + 2]; v.w = acc[i][j + 3];
            if (bias) {
                v.x += bias[col + 0]; v.y += bias[col + 1];
                v.z += bias[col + 2]; v.w += bias[col + 3];
            }
            *(float4*)&C[row * Ndim + col] = v;
        }
    }
}

// ---------------- scores[b,h*64+m,n] = sum_d wtq[h,m,d] * xk[b,h,n,d] ----------------
// xk[b,h,n,d] = kv[(b*N+n)*1024 + h*64 + d]
__global__ __launch_bounds__(256)
void scores_kernel(const float* __restrict__ kv, const float* __restrict__ wtq,
                   float* __restrict__ scores)
{
    int bh = blockIdx.y; int b = bh >> 3, h = bh & 7;
    int n0 = blockIdx.x * 64;
    __shared__ float wts[64][68];   // [m][d]
    __shared__ float xs[64][68];    // [n][d]
    int tid = threadIdx.x;

    const float* wq = wtq + (long long)h * 4096;
#pragma unroll
    for (int i = 0; i < 4; i++) {
        int idx = tid + i * 256;    // 0..1023
        int m = idx >> 4, c4 = idx & 15;
        *(float4*)&wts[m][c4 * 4] = *(const float4*)&wq[m * 64 + c4 * 4];
    }
    const float* xk = kv + (long long)b * NN * 1024 + h * 64;
#pragma unroll
    for (int i = 0; i < 4; i++) {
        int idx = tid + i * 256;
        int n = idx >> 4, c4 = idx & 15;
        *(float4*)&xs[n][c4 * 4] = *(const float4*)&xk[(long long)(n0 + n) * 1024 + c4 * 4];
    }
    __syncthreads();

    int tx = tid & 15, ty = tid >> 4;  // tx->n(4), ty->m(4)
    float acc[4][4];
#pragma unroll
    for (int i = 0; i < 4; i++)
#pragma unroll
        for (int j = 0; j < 4; j++) acc[i][j] = 0.f;

#pragma unroll
    for (int d = 0; d < 64; d += 4) {
        float4 ra[4], rb[4];
#pragma unroll
        for (int i = 0; i < 4; i++) ra[i] = *(float4*)&wts[ty * 4 + i][d];
#pragma unroll
        for (int j = 0; j < 4; j++) rb[j] = *(float4*)&xs[tx * 4 + j][d];
#pragma unroll
        for (int i = 0; i < 4; i++)
#pragma unroll
            for (int j = 0; j < 4; j++)
                acc[i][j] += ra[i].x * rb[j].x + ra[i].y * rb[j].y +
                             ra[i].z * rb[j].z + ra[i].w * rb[j].w;
    }
    float* sc = scores + ((long long)b * 512 + h * 64) * NN + n0;
#pragma unroll
    for (int i = 0; i < 4; i++) {
        float4 v = {acc[i][0], acc[i][1], acc[i][2], acc[i][3]};
        *(float4*)&sc[(long long)(ty * 4 + i) * NN + tx * 4] = v;
    }
}

// ---------------- softmax over m (64 values, stride N) ----------------
__global__ __launch_bounds__(256)
void softmax_kernel(float* __restrict__ sc)
{
    int bh = blockIdx.y; int b = bh >> 3, h = bh & 7;
    int n = blockIdx.x * 256 + threadIdx.x;
    float* p = sc + ((long long)b * 512 + h * 64) * NN + n;
    float v[64];
#pragma unroll
    for (int m = 0; m < 64; m++) v[m] = p[(long long)m * NN];
    float mx = v[0];
#pragma unroll
    for (int m = 1; m < 64; m++) mx = fmaxf(mx, v[m]);
    float s = 0.f;
#pragma unroll
    for (int m = 0; m < 64; m++) { v[m] = __expf(v[m] - mx); s += v[m]; }
    float inv = 1.0f / s;
#pragma unroll
    for (int m = 0; m < 64; m++) p[(long long)m * NN] = v[m] * inv;
}

// ---------------- sumw[b*512+c] = sum_n slice_w[b,c,n] ----------------
__global__ __launch_bounds__(256)
void sumw_kernel(const float* __restrict__ sw, float* __restrict__ sumw)
{
    int bc = blockIdx.x;
    const float* p = sw + (long long)bc * NN;
    float s = 0.f;
    for (int n = threadIdx.x; n < NN; n += 256) s += p[n];
    __shared__ float red[256];
    red[threadIdx.x] = s; __syncthreads();
    for (int off = 128; off > 0; off >>= 1) {
        if (threadIdx.x < off) red[threadIdx.x] += red[threadIdx.x + off];
        __syncthreads();
    }
    if (threadIdx.x == 0) sumw[bc] = red[0];
}

// ---------------- slice_tok partials: deterministic split-K over n ----------------
// part[bh][split][m*64+d] = sum_{n in split} slice_w[b,h*64+m,n] * xv[b,h,n,d]
__global__ __launch_bounds__(256)
void stok_part_kernel(const float* __restrict__ sw, const float* __restrict__ kv,
                      float* __restrict__ part)
{
    int bh = blockIdx.y; int b = bh >> 3, h = bh & 7;
    int split = blockIdx.x;                 // 0..15, each covers 512 n
    __shared__ float sws[64][68];           // [m][n]
    __shared__ float xvs[64][64];           // [n][d]
    int tid = threadIdx.x;
    int tx = tid & 15, ty = tid >> 4;       // tx->d(4), ty->m(4)

    float acc[4][4];
#pragma unroll
    for (int i = 0; i < 4; i++)
#pragma unroll
        for (int j = 0; j < 4; j++) acc[i][j] = 0.f;

    const float* swb = sw + ((long long)b * 512 + h * 64) * NN;
    const float* xvb = kv + (long long)b * NN * 1024 + 512 + h * 64;

    for (int c = 0; c < 8; c++) {
        int n0 = split * 512 + c * 64;
#pragma unroll
        for (int i = 0; i < 4; i++) {
            int idx = tid + i * 256;
            int m = idx >> 4, c4 = idx & 15;
            *(float4*)&sws[m][c4 * 4] = *(const float4*)&swb[(long long)m * NN + n0 + c4 * 4];
        }
#pragma unroll
        for (int i = 0; i < 4; i++) {
            int idx = tid + i * 256;
            int n = idx >> 4, c4 = idx & 15;
            *(float4*)&xvs[n][c4 * 4] = *(const float4*)&xvb[(long long)(n0 + n) * 1024 + c4 * 4];
        }
        __syncthreads();
#pragma unroll 4
        for (int n = 0; n < 64; n++) {
            float rm[4];
#pragma unroll
            for (int i = 0; i < 4; i++) rm[i] = sws[ty * 4 + i][n];
            float4 rd = *(float4*)&xvs[n][tx * 4];
#pragma unroll
            for (int i = 0; i < 4; i++) {
                acc[i][0] += rm[i] * rd.x; acc[i][1] += rm[i] * rd.y;
                acc[i][2] += rm[i] * rd.z; acc[i][3] += rm[i] * rd.w;
            }
        }
        __syncthreads();
    }
    float* pp = part + ((long long)bh * 16 + split) * 4096;
#pragma unroll
    for (int i = 0; i < 4; i++) {
        float4 v = {acc[i][0], acc[i][1], acc[i][2], acc[i][3]};
        *(float4*)&pp[(ty * 4 + i) * 64 + tx * 4] = v;
    }
}

__global__ __launch_bounds__(256)
void stok_reduce_kernel(const float* __restrict__ part, float* __restrict__ stok)
{
    int bh = blockIdx.x;
    for (int i = threadIdx.x; i < 4096; i += 256) {
        float s = 0.f;
#pragma unroll
        for (int sp = 0; sp < 16; sp++) s += part[((long long)bh * 16 + sp) * 4096 + i];
        stok[(long long)bh * 4096 + i] = s;
    }
}

// ---------------- normalize by sumw + layernorm -> st[b,m,h*64+d] ----------------
__global__ __launch_bounds__(256)
void ln_kernel(const float* __restrict__ stok, const float* __restrict__ sumw,
               const float* __restrict__ gg, const float* __restrict__ bta,
               float* __restrict__ st)
{
    int warp = (blockIdx.x * blockDim.x + threadIdx.x) >> 5;  // 0..4095 = bh*64+m
    int lane = threadIdx.x & 31;
    int m = warp & 63, h = (warp >> 6) & 7, b = warp >> 9;

    float inv = 1.0f / (sumw[warp] + 1e-5f);
    const float* sp = stok + (long long)warp * 64;
    float x0 = sp[lane] * inv, x1 = sp[lane + 32] * inv;
    float s = x0 + x1;
#pragma unroll
    for (int o = 16; o; o >>= 1) s += __shfl_xor_sync(0xffffffffu, s, o);
    float mu = s * (1.0f / 64.0f);
    float d0 = x0 - mu, d1 = x1 - mu;
    float vs = d0 * d0 + d1 * d1;
#pragma unroll
    for (int o = 16; o; o >>= 1) vs += __shfl_xor_sync(0xffffffffu, vs, o);
    float rstd = rsqrtf(vs * (1.0f / 64.0f) + 1e-5f);
    float y0 = d0 * rstd * gg[lane] + bta[lane];
    float y1 = d1 * rstd * gg[lane + 32] + bta[lane + 32];
    float* op = st + ((long long)(b * 64 + m)) * 512 + h * 64;
    op[lane] = y0; op[lane + 32] = y1;
}

// ---------------- mini self-attention over M=64 tokens, one block per (b,h) ----------------
__global__ __launch_bounds__(256)
void attn_kernel(const float* __restrict__ qkv, float* __restrict__ otok)
{
    int bh = blockIdx.x; int b = bh >> 3, h = bh & 7;
    __shared__ float qs[64][68];
    __shared__ float ks[64][68];
    int tid = threadIdx.x;
    const float* base = qkv + (long long)b * 64 * 1536 + h * 64;

#pragma unroll
    for (int i = 0; i < 4; i++) {
        int idx = tid + i * 256;
        int m = idx >> 4, c4 = idx & 15;
        *(float4*)&qs[m][c4 * 4] = *(const float4*)&base[(long long)m * 1536 + c4 * 4];
        *(float4*)&ks[m][c4 * 4] = *(const float4*)&base[(long long)m * 1536 + 512 + c4 * 4];
    }
    __syncthreads();

    int tx = tid & 15, ty = tid >> 4;   // tx->k(4), ty->q(4)
    float dots[4][4];
#pragma unroll
    for (int i = 0; i < 4; i++)
#pragma unroll
        for (int j = 0; j < 4; j++) dots[i][j] = 0.f;
#pragma unroll
    for (int d = 0; d < 64; d += 4) {
        float4 ra[4], rb[4];
#pragma unroll
        for (int i = 0; i < 4; i++) ra[i] = *(float4*)&qs[ty * 4 + i][d];
#pragma unroll
        for (int j = 0; j < 4; j++) rb[j] = *(float4*)&ks[tx * 4 + j][d];
#pragma unroll
        for (int i = 0; i < 4; i++)
#pragma unroll
            for (int j = 0; j < 4; j++)
                dots[i][j] += ra[i].x * rb[j].x + ra[i].y * rb[j].y +
                              ra[i].z * rb[j].z + ra[i].w * rb[j].w;
    }
    __syncthreads();
    // overwrite qs with scaled dots; load v into ks
#pragma unroll
    for (int i = 0; i < 4; i++)
#pragma unroll
        for (int j = 0; j < 4; j++)
            qs[ty * 4 + i][tx * 4 + j] = dots[i][j] * 0.125f;   // 64^-0.5
#pragma unroll
    for (int i = 0; i < 4; i++) {
        int idx = tid + i * 256;
        int m = idx >> 4, c4 = idx & 15;
        *(float4*)&ks[m][c4 * 4] = *(const float4*)&base[(long long)m * 1536 + 1024 + c4 * 4];
    }
    __syncthreads();

    // softmax over k for each row (8 warps x 8 rows)
    int wid = tid >> 5, lane = tid & 31;
#pragma unroll
    for (int r = 0; r < 8; r++) {
        int m = wid * 8 + r;
        float a0 = qs[m][lane], a1 = qs[m][lane + 32];
        float mx = fmaxf(a0, a1);
#pragma unroll
        for (int o = 16; o; o >>= 1) mx = fmaxf(mx, __shfl_xor_sync(0xffffffffu, mx, o));
        float e0 = __expf(a0 - mx), e1 = __expf(a1 - mx);
        float s = e0 + e1;
#pragma unroll
        for (int o = 16; o; o >>= 1) s += __shfl_xor_sync(0xffffffffu, s, o);
        float inv = 1.0f / s;
        qs[m][lane] = e0 * inv; qs[m][lane + 32] = e1 * inv;
    }
    __syncthreads();

    // out = attn @ v ; tx->d(4), ty->q(4)
    float acc[4][4];
#pragma unroll
    for (int i = 0; i < 4; i++)
#pragma unroll
        for (int j = 0; j < 4; j++) acc[i][j] = 0.f;
#pragma unroll 4
    for (int k = 0; k < 64; k++) {
        float rm[4];
#pragma unroll
        for (int i = 0; i < 4; i++) rm[i] = qs[ty * 4 + i][k];
        float4 rv = *(float4*)&ks[k][tx * 4];
#pragma unroll
        for (int i = 0; i < 4; i++) {
            acc[i][0] += rm[i] * rv.x; acc[i][1] += rm[i] * rv.y;
            acc[i][2] += rm[i] * rv.z; acc[i][3] += rm[i] * rv.w;
        }
    }
    float* op = otok + (long long)bh * 4096;
#pragma unroll
    for (int i = 0; i < 4; i++) {
        float4 v = {acc[i][0], acc[i][1], acc[i][2], acc[i][3]};
        *(float4*)&op[(ty * 4 + i) * 64 + tx * 4] = v;
    }
}

// ---------------- scatter: pre[b,n,h*64+d] = sum_m otok[b,h,m,d] * slice_w[b,h*64+m,n] ----------------
__global__ __launch_bounds__(256)
void scatter_kernel(const float* __restrict__ sw, const float* __restrict__ otok,
                    float* __restrict__ pre)
{
    int bh = blockIdx.y; int b = bh >> 3, h = bh & 7;
    int n0 = blockIdx.x * 64;
    __shared__ float sws[64][68];   // [m][n]
    __shared__ float ots[64][64];   // [m][d]
    int tid = threadIdx.x;

    const float* swb = sw + ((long long)b * 512 + h * 64) * NN;
#pragma unroll
    for (int i = 0; i < 4; i++) {
        int idx = tid + i * 256;
        int m = idx >> 4, c4 = idx & 15;
        *(float4*)&sws[m][c4 * 4] = *(const float4*)&swb[(long long)m * NN + n0 + c4 * 4];
        *(float4*)&ots[m][c4 * 4] = *(const float4*)&otok[(long long)bh * 4096 + m * 64 + c4 * 4];
    }
    __syncthreads();

    int tx = tid & 15, ty = tid >> 4;   // tx->d(4), ty->n(4)
    float acc[4][4];
#pragma unroll
    for (int i = 0; i < 4; i++)
#pragma unroll
        for (int j = 0; j < 4; j++) acc[i][j] = 0.f;
#pragma unroll 4
    for (int m = 0; m < 64; m++) {
        float rn[4];
#pragma unroll
        for (int i = 0; i < 4; i++) rn[i] = sws[m][ty * 4 + i];
        float4 rd = *(float4*)&ots[m][tx * 4];
#pragma unroll
        for (int i = 0; i < 4; i++) {
            acc[i][0] += rn[i] * rd.x; acc[i][1] += rn[i] * rd.y;
            acc[i][2] += rn[i] * rd.z; acc[i][3] += rn[i] * rd.w;
        }
    }
    float* pb = pre + (long long)b * NN * 512 + h * 64;
#pragma unroll
    for (int i = 0; i < 4; i++) {
        long long n = n0 + ty * 4 + i;
        float4 v = {acc[i][0], acc[i][1], acc[i][2], acc[i][3]};
        *(float4*)&pb[n * 512 + tx * 4] = v;
    }
}

// ---------------- launch ----------------
extern "C" void kernel_launch(void* const* d_in, const int* in_sizes, int n_in,
                              void* d_out, int out_size)
{
    (void)in_sizes; (void)n_in; (void)out_size;
    const float* x     = (const float*)d_in[0];
    const float* W_kv  = (const float*)d_in[1];
    const float* b_kv  = (const float*)d_in[2];
    const float* wtq   = (const float*)d_in[3];
    const float* W_mix = (const float*)d_in[4];
    const float* ln_g  = (const float*)d_in[5];
    const float* ln_b  = (const float*)d_in[6];
    const float* W_qkv = (const float*)d_in[7];
    const float* W_out = (const float*)d_in[8];
    const float* b_out = (const float*)d_in[9];
    float* out = (float*)d_out;

    float *kv, *scores, *mixed, *sumw, *part, *stok, *st, *qkv, *otok, *pre;
    cudaGetSymbolAddress((void**)&kv, g_kv);
    cudaGetSymbolAddress((void**)&scores, g_scores);
    cudaGetSymbolAddress((void**)&mixed, g_mixed);
    cudaGetSymbolAddress((void**)&sumw, g_sumw);
    cudaGetSymbolAddress((void**)&part, g_part);
    cudaGetSymbolAddress((void**)&stok, g_stok);
    cudaGetSymbolAddress((void**)&st, g_st);
    cudaGetSymbolAddress((void**)&qkv, g_qkv);
    cudaGetSymbolAddress((void**)&otok, g_otok);
    cudaGetSymbolAddress((void**)&pre, g_pre);

    // 1) kv = x @ W_kv + b_kv              [65536,512] x [512,1024]
    sgemm_kernel<<<dim3(1024 / 128, 65536 / 128, 1), 256>>>(
        x, W_kv, b_kv, kv, 65536, 1024, 512, 0, 0, 0);

    // 2) scores = wtq . xk                 per (b,h): [64,64] x [64,8192]
    scores_kernel<<<dim3(NN / 64, 64), 256>>>(kv, wtq, scores);

    // 3) mixed = W_mix @ scores            per b: [512,512] x [512,8192]
    sgemm_kernel<<<dim3(NN / 128, 512 / 128, BB), 256>>>(
        W_mix, scores, nullptr, mixed, 512, NN, 512,
        0, (long long)512 * NN, (long long)512 * NN);

    // 4) softmax over m (in place -> slice_w)
    softmax_kernel<<<dim3(NN / 256, 64), 256>>>(mixed);

    // 4b) sumw over n
    sumw_kernel<<<4096, 256>>>(mixed, sumw);

    // 5) slice_tok = slice_w @ xv (deterministic split-K)
    stok_part_kernel<<<dim3(16, 64), 256>>>(mixed, kv, part);
    stok_reduce_kernel<<<64, 256>>>(part, stok);

    // 6) normalize + layernorm -> st[B,M,D]
    ln_kernel<<<512, 256>>>(stok, sumw, ln_g, ln_b, st);

    // 7) qkv = st @ W_qkv                  [512,512] x [512,1536]
    sgemm_kernel<<<dim3(1536 / 128, 512 / 128, 1), 256>>>(
        st, W_qkv, nullptr, qkv, 512, 1536, 512, 0, 0, 0);

    // 8) mini self-attention over M
    attn_kernel<<<64, 256>>>(qkv, otok);

    // 9) scatter: pre = otok^T applied through slice_w
    scatter_kernel<<<dim3(NN / 64, 64), 256>>>(mixed, otok, pre);

    // 10) out = pre @ W_out + b_out        [65536,512] x [512,512]
    sgemm_kernel<<<dim3(512 / 128, 65536 / 128, 1), 256>>>(
        pre, W_out, b_out, out, 65536, 512, 512, 0, 0, 0);
}

// round 4
// speedup vs baseline: 2.1560x; 2.1560x over previous
#include <cuda_runtime.h>
#include <cstdint>

// ---------------- constants ----------------
#define BB 8
#define NN 8192

// ---------------- device scratch (no allocs allowed) ----------------
__device__ float g_kv[67108864];        // [B,N,2D]  256MB
__device__ float g_scores[33554432];    // [B,512,N] 128MB
__device__ float g_mixed[33554432];     // [B,512,N] 128MB (becomes slice_w in place)
__device__ float g_sumw[4096];          // [B,512]
__device__ float g_part[4194304];       // [64 bh][16 splits][64*64]
__device__ float g_stok[262144];        // [B,H,M,HD]
__device__ float g_st[262144];          // [B,M,D]
__device__ float g_qkv[786432];         // [B*M, 1536]
__device__ float g_otok[262144];        // [B,H,M,HD]
__device__ float g_pre[33554432];       // [B,N,D] 128MB

__device__ __forceinline__ float to_tf32(float x) {
    float r; asm("cvt.rna.tf32.f32 %0, %1;" : "=f"(r) : "f"(x)); return r;
}
__device__ __forceinline__ void mma_tf32(float& d0, float& d1, float& d2, float& d3,
                                         uint32_t a0, uint32_t a1, uint32_t a2, uint32_t a3,
                                         uint32_t b0, uint32_t b1) {
    asm volatile(
        "mma.sync.aligned.m16n8k8.row.col.f32.tf32.tf32.f32 "
        "{%0,%1,%2,%3}, {%4,%5,%6,%7}, {%8,%9}, {%0,%1,%2,%3};"
        : "+f"(d0), "+f"(d1), "+f"(d2), "+f"(d3)
        : "r"(a0), "r"(a1), "r"(a2), "r"(a3), "r"(b0), "r"(b1));
}

// ---------------- tf32 mma.sync GEMM: C = A[M,K] @ B[K,N] (+bias) ----------------
// 128x128 tile, BK=16, 256 threads (8 warps, warp tile 64x32).
// A smem stride 20 floats, B smem stride 136 floats -> conflict-free frag loads.
#define ASTR 20
#define BSTR 136
__global__ __launch_bounds__(256)
void mma_gemm_kernel(const float* __restrict__ A, const float* __restrict__ Bm,
                     const float* __restrict__ bias, float* __restrict__ C,
                     int Nd, int Kd, long long Abs, long long Bbs, long long Cbs)
{
    A  += blockIdx.z * Abs;
    Bm += blockIdx.z * Bbs;
    C  += blockIdx.z * Cbs;

    __shared__ float As[2][128 * ASTR];
    __shared__ float Bs[2][16 * BSTR];

    const int tid = threadIdx.x;
    const int lane = tid & 31, wid = tid >> 5;
    const int wm = wid & 1, wn = wid >> 1;       // 2 x 4 warp grid
    const int g = lane >> 2, t = lane & 3;
    const int m0 = blockIdx.y * 128, n0 = blockIdx.x * 128;

    float acc[4][4][4];
#pragma unroll
    for (int i = 0; i < 4; i++)
#pragma unroll
        for (int j = 0; j < 4; j++)
#pragma unroll
            for (int r = 0; r < 4; r++) acc[i][j][r] = 0.f;

    // loader mappings
    const int ar[2] = { (tid + 0) >> 2, (tid + 256) >> 2 };        // A row 0..127
    const int ac = (tid & 3) * 4;                                   // A col 0..12
    const int br[2] = { (tid + 0) >> 5, (tid + 256) >> 5 };        // B row 0..15
    const int bc = (tid & 31) * 4;                                  // B col 0..124

    float4 ra[2], rb[2];
    const int NK = Kd >> 4;

    // prologue: load tile 0
#pragma unroll
    for (int i = 0; i < 2; i++)
        ra[i] = *(const float4*)&A[(long long)(m0 + ar[i]) * Kd + ac];
#pragma unroll
    for (int i = 0; i < 2; i++)
        rb[i] = *(const float4*)&Bm[(long long)br[i] * Nd + n0 + bc];
#pragma unroll
    for (int i = 0; i < 2; i++) {
        float4 v = ra[i];
        As[0][ar[i] * ASTR + ac + 0] = to_tf32(v.x);
        As[0][ar[i] * ASTR + ac + 1] = to_tf32(v.y);
        As[0][ar[i] * ASTR + ac + 2] = to_tf32(v.z);
        As[0][ar[i] * ASTR + ac + 3] = to_tf32(v.w);
        float4 w = rb[i];
        Bs[0][br[i] * BSTR + bc + 0] = to_tf32(w.x);
        Bs[0][br[i] * BSTR + bc + 1] = to_tf32(w.y);
        Bs[0][br[i] * BSTR + bc + 2] = to_tf32(w.z);
        Bs[0][br[i] * BSTR + bc + 3] = to_tf32(w.w);
    }
    __syncthreads();

    for (int ck = 0; ck < NK; ck++) {
        const int buf = ck & 1;
        const bool more = (ck + 1) < NK;
        if (more) {
            int kt = (ck + 1) * 16;
#pragma unroll
            for (int i = 0; i < 2; i++)
                ra[i] = *(const float4*)&A[(long long)(m0 + ar[i]) * Kd + kt + ac];
#pragma unroll
            for (int i = 0; i < 2; i++)
                rb[i] = *(const float4*)&Bm[(long long)(kt + br[i]) * Nd + n0 + bc];
        }

        // compute: 2 k-steps of 8
#pragma unroll
        for (int s = 0; s < 2; s++) {
            const int k0 = s * 8;
            uint32_t af[4][4];
#pragma unroll
            for (int i = 0; i < 4; i++) {
                int r0 = (wm * 64 + i * 16 + g) * ASTR + k0 + t;
                int r1 = r0 + 8 * ASTR;
                af[i][0] = __float_as_uint(As[buf][r0]);
                af[i][1] = __float_as_uint(As[buf][r1]);
                af[i][2] = __float_as_uint(As[buf][r0 + 4]);
                af[i][3] = __float_as_uint(As[buf][r1 + 4]);
            }
            uint32_t bf[4][2];
#pragma unroll
            for (int j = 0; j < 4; j++) {
                int col = wn * 32 + j * 8 + g;
                bf[j][0] = __float_as_uint(Bs[buf][(k0 + t) * BSTR + col]);
                bf[j][1] = __float_as_uint(Bs[buf][(k0 + t + 4) * BSTR + col]);
            }
#pragma unroll
            for (int i = 0; i < 4; i++)
#pragma unroll
                for (int j = 0; j < 4; j++)
                    mma_tf32(acc[i][j][0], acc[i][j][1], acc[i][j][2], acc[i][j][3],
                             af[i][0], af[i][1], af[i][2], af[i][3],
                             bf[j][0], bf[j][1]);
        }

        if (more) {
            const int nb = buf ^ 1;
#pragma unroll
            for (int i = 0; i < 2; i++) {
                float4 v = ra[i];
                As[nb][ar[i] * ASTR + ac + 0] = to_tf32(v.x);
                As[nb][ar[i] * ASTR + ac + 1] = to_tf32(v.y);
                As[nb][ar[i] * ASTR + ac + 2] = to_tf32(v.z);
                As[nb][ar[i] * ASTR + ac + 3] = to_tf32(v.w);
                float4 w = rb[i];
                Bs[nb][br[i] * BSTR + bc + 0] = to_tf32(w.x);
                Bs[nb][br[i] * BSTR + bc + 1] = to_tf32(w.y);
                Bs[nb][br[i] * BSTR + bc + 2] = to_tf32(w.z);
                Bs[nb][br[i] * BSTR + bc + 3] = to_tf32(w.w);
            }
            __syncthreads();
        }
    }

    // epilogue
#pragma unroll
    for (int i = 0; i < 4; i++) {
#pragma unroll
        for (int j = 0; j < 4; j++) {
            int col = n0 + wn * 32 + j * 8 + t * 2;
            float bx = 0.f, by = 0.f;
            if (bias) { bx = bias[col]; by = bias[col + 1]; }
            long long row0 = m0 + wm * 64 + i * 16 + g;
            float2 v0 = { acc[i][j][0] + bx, acc[i][j][1] + by };
            float2 v1 = { acc[i][j][2] + bx, acc[i][j][3] + by };
            *(float2*)&C[row0 * Nd + col] = v0;
            *(float2*)&C[(row0 + 8) * Nd + col] = v1;
        }
    }
}

// ---------------- SIMT tiled SGEMM (kept for the tiny qkv GEMM) ----------------
__global__ __launch_bounds__(256)
void sgemm_kernel(const float* __restrict__ A, const float* __restrict__ Bm,
                  const float* __restrict__ bias, float* __restrict__ C,
                  int Mdim, int Ndim, int Kdim,
                  long long Abs, long long Bbs, long long Cbs)
{
    const int bz = blockIdx.z;
    A  += bz * Abs;
    Bm += bz * Bbs;
    C  += bz * Cbs;

    __shared__ float Asm[16][128];
    __shared__ float Bsm[16][128];

    const int tid = threadIdx.x;
    const int tx = tid & 15, ty = tid >> 4;
    const int m0 = blockIdx.y * 128, n0 = blockIdx.x * 128;

    float acc[8][8];
#pragma unroll
    for (int i = 0; i < 8; i++)
#pragma unroll
        for (int j = 0; j < 8; j++) acc[i][j] = 0.f;

    for (int kt = 0; kt < Kdim; kt += 16) {
#pragma unroll
        for (int i = 0; i < 2; i++) {
            int idx = tid + i * 256;
            int r = idx >> 2;
            int c4 = idx & 3;
            float4 v = *(const float4*)&A[(long long)(m0 + r) * Kdim + kt + c4 * 4];
            Asm[c4 * 4 + 0][r] = v.x;
            Asm[c4 * 4 + 1][r] = v.y;
            Asm[c4 * 4 + 2][r] = v.z;
            Asm[c4 * 4 + 3][r] = v.w;
        }
#pragma unroll
        for (int i = 0; i < 2; i++) {
            int idx = tid + i * 256;
            int r = idx >> 5;
            int c4 = idx & 31;
            *(float4*)&Bsm[r][c4 * 4] =
                *(const float4*)&Bm[(long long)(kt + r) * Ndim + n0 + c4 * 4];
        }
        __syncthreads();
#pragma unroll
        for (int k = 0; k < 16; k++) {
            float4 a0 = *(float4*)&Asm[k][ty * 8];
            float4 a1 = *(float4*)&Asm[k][ty * 8 + 4];
            float4 b0 = *(float4*)&Bsm[k][tx * 8];
            float4 b1 = *(float4*)&Bsm[k][tx * 8 + 4];
            float ra[8] = {a0.x, a0.y, a0.z, a0.w, a1.x, a1.y, a1.z, a1.w};
            float rb[8] = {b0.x, b0.y, b0.z, b0.w, b1.x, b1.y, b1.z, b1.w};
#pragma unroll
            for (int i = 0; i < 8; i++)
#pragma unroll
                for (int j = 0; j < 8; j++) acc[i][j] += ra[i] * rb[j];
        }
        __syncthreads();
    }

#pragma unroll
    for (int i = 0; i < 8; i++) {
        long long row = m0 + ty * 8 + i;
#pragma unroll
        for (int j = 0; j < 8; j += 4) {
            int col = n0 + tx * 8 + j;
            float4 v;
            v.x = acc[i][j + 0]; v.y = acc[i][j + 1];
            v.z = acc[i][j + 2]; v.w = acc[i][j + 3];
            if (bias) {
                v.x += bias[col + 0]; v.y += bias[col + 1];
                v.z += bias[col + 2]; v.w += bias[col + 3];
            }
            *(float4*)&C[row * Ndim + col] = v;
        }
    }
}

// ---------------- scores[b,h*64+m,n] = sum_d wtq[h,m,d] * xk[b,h,n,d] ----------------
__global__ __launch_bounds__(256)
void scores_kernel(const float* __restrict__ kv, const float* __restrict__ wtq,
                   float* __restrict__ scores)
{
    int bh = blockIdx.y; int b = bh >> 3, h = bh & 7;
    int n0 = blockIdx.x * 64;
    __shared__ float wts[64][68];
    __shared__ float xs[64][68];
    int tid = threadIdx.x;

    const float* wq = wtq + (long long)h * 4096;
#pragma unroll
    for (int i = 0; i < 4; i++) {
        int idx = tid + i * 256;
        int m = idx >> 4, c4 = idx & 15;
        *(float4*)&wts[m][c4 * 4] = *(const float4*)&wq[m * 64 + c4 * 4];
    }
    const float* xk = kv + (long long)b * NN * 1024 + h * 64;
#pragma unroll
    for (int i = 0; i < 4; i++) {
        int idx = tid + i * 256;
        int n = idx >> 4, c4 = idx & 15;
        *(float4*)&xs[n][c4 * 4] = *(const float4*)&xk[(long long)(n0 + n) * 1024 + c4 * 4];
    }
    __syncthreads();

    int tx = tid & 15, ty = tid >> 4;
    float acc[4][4];
#pragma unroll
    for (int i = 0; i < 4; i++)
#pragma unroll
        for (int j = 0; j < 4; j++) acc[i][j] = 0.f;

#pragma unroll
    for (int d = 0; d < 64; d += 4) {
        float4 ra[4], rb[4];
#pragma unroll
        for (int i = 0; i < 4; i++) ra[i] = *(float4*)&wts[ty * 4 + i][d];
#pragma unroll
        for (int j = 0; j < 4; j++) rb[j] = *(float4*)&xs[tx * 4 + j][d];
#pragma unroll
        for (int i = 0; i < 4; i++)
#pragma unroll
            for (int j = 0; j < 4; j++)
                acc[i][j] += ra[i].x * rb[j].x + ra[i].y * rb[j].y +
                             ra[i].z * rb[j].z + ra[i].w * rb[j].w;
    }
    float* sc = scores + ((long long)b * 512 + h * 64) * NN + n0;
#pragma unroll
    for (int i = 0; i < 4; i++) {
        float4 v = {acc[i][0], acc[i][1], acc[i][2], acc[i][3]};
        *(float4*)&sc[(long long)(ty * 4 + i) * NN + tx * 4] = v;
    }
}

// ---------------- softmax over m (64 values, stride N) ----------------
__global__ __launch_bounds__(256)
void softmax_kernel(float* __restrict__ sc)
{
    int bh = blockIdx.y; int b = bh >> 3, h = bh & 7;
    int n = blockIdx.x * 256 + threadIdx.x;
    float* p = sc + ((long long)b * 512 + h * 64) * NN + n;
    float v[64];
#pragma unroll
    for (int m = 0; m < 64; m++) v[m] = p[(long long)m * NN];
    float mx = v[0];
#pragma unroll
    for (int m = 1; m < 64; m++) mx = fmaxf(mx, v[m]);
    float s = 0.f;
#pragma unroll
    for (int m = 0; m < 64; m++) { v[m] = __expf(v[m] - mx); s += v[m]; }
    float inv = 1.0f / s;
#pragma unroll
    for (int m = 0; m < 64; m++) p[(long long)m * NN] = v[m] * inv;
}

// ---------------- sumw[b*512+c] = sum_n slice_w[b,c,n] ----------------
__global__ __launch_bounds__(256)
void sumw_kernel(const float* __restrict__ sw, float* __restrict__ sumw)
{
    int bc = blockIdx.x;
    const float* p = sw + (long long)bc * NN;
    float s = 0.f;
    for (int n = threadIdx.x; n < NN; n += 256) s += p[n];
    __shared__ float red[256];
    red[threadIdx.x] = s; __syncthreads();
    for (int off = 128; off > 0; off >>= 1) {
        if (threadIdx.x < off) red[threadIdx.x] += red[threadIdx.x + off];
        __syncthreads();
    }
    if (threadIdx.x == 0) sumw[bc] = red[0];
}

// ---------------- slice_tok partials: deterministic split-K over n ----------------
__global__ __launch_bounds__(256)
void stok_part_kernel(const float* __restrict__ sw, const float* __restrict__ kv,
                      float* __restrict__ part)
{
    int bh = blockIdx.y; int b = bh >> 3, h = bh & 7;
    int split = blockIdx.x;
    __shared__ float sws[64][68];
    __shared__ float xvs[64][64];
    int tid = threadIdx.x;
    int tx = tid & 15, ty = tid >> 4;

    float acc[4][4];
#pragma unroll
    for (int i = 0; i < 4; i++)
#pragma unroll
        for (int j = 0; j < 4; j++) acc[i][j] = 0.f;

    const float* swb = sw + ((long long)b * 512 + h * 64) * NN;
    const float* xvb = kv + (long long)b * NN * 1024 + 512 + h * 64;

    for (int c = 0; c < 8; c++) {
        int n0 = split * 512 + c * 64;
#pragma unroll
        for (int i = 0; i < 4; i++) {
            int idx = tid + i * 256;
            int m = idx >> 4, c4 = idx & 15;
            *(float4*)&sws[m][c4 * 4] = *(const float4*)&swb[(long long)m * NN + n0 + c4 * 4];
        }
#pragma unroll
        for (int i = 0; i < 4; i++) {
            int idx = tid + i * 256;
            int n = idx >> 4, c4 = idx & 15;
            *(float4*)&xvs[n][c4 * 4] = *(const float4*)&xvb[(long long)(n0 + n) * 1024 + c4 * 4];
        }
        __syncthreads();
#pragma unroll 4
        for (int n = 0; n < 64; n++) {
            float rm[4];
#pragma unroll
            for (int i = 0; i < 4; i++) rm[i] = sws[ty * 4 + i][n];
            float4 rd = *(float4*)&xvs[n][tx * 4];
#pragma unroll
            for (int i = 0; i < 4; i++) {
                acc[i][0] += rm[i] * rd.x; acc[i][1] += rm[i] * rd.y;
                acc[i][2] += rm[i] * rd.z; acc[i][3] += rm[i] * rd.w;
            }
        }
        __syncthreads();
    }
    float* pp = part + ((long long)bh * 16 + split) * 4096;
#pragma unroll
    for (int i = 0; i < 4; i++) {
        float4 v = {acc[i][0], acc[i][1], acc[i][2], acc[i][3]};
        *(float4*)&pp[(ty * 4 + i) * 64 + tx * 4] = v;
    }
}

__global__ __launch_bounds__(256)
void stok_reduce_kernel(const float* __restrict__ part, float* __restrict__ stok)
{
    int bh = blockIdx.x;
    for (int i = threadIdx.x; i < 4096; i += 256) {
        float s = 0.f;
#pragma unroll
        for (int sp = 0; sp < 16; sp++) s += part[((long long)bh * 16 + sp) * 4096 + i];
        stok[(long long)bh * 4096 + i] = s;
    }
}

// ---------------- normalize by sumw + layernorm -> st[b,m,h*64+d] ----------------
__global__ __launch_bounds__(256)
void ln_kernel(const float* __restrict__ stok, const float* __restrict__ sumw,
               const float* __restrict__ gg, const float* __restrict__ bta,
               float* __restrict__ st)
{
    int warp = (blockIdx.x * blockDim.x + threadIdx.x) >> 5;
    int lane = threadIdx.x & 31;
    int m = warp & 63, h = (warp >> 6) & 7, b = warp >> 9;

    float inv = 1.0f / (sumw[warp] + 1e-5f);
    const float* sp = stok + (long long)warp * 64;
    float x0 = sp[lane] * inv, x1 = sp[lane + 32] * inv;
    float s = x0 + x1;
#pragma unroll
    for (int o = 16; o; o >>= 1) s += __shfl_xor_sync(0xffffffffu, s, o);
    float mu = s * (1.0f / 64.0f);
    float d0 = x0 - mu, d1 = x1 - mu;
    float vs = d0 * d0 + d1 * d1;
#pragma unroll
    for (int o = 16; o; o >>= 1) vs += __shfl_xor_sync(0xffffffffu, vs, o);
    float rstd = rsqrtf(vs * (1.0f / 64.0f) + 1e-5f);
    float y0 = d0 * rstd * gg[lane] + bta[lane];
    float y1 = d1 * rstd * gg[lane + 32] + bta[lane + 32];
    float* op = st + ((long long)(b * 64 + m)) * 512 + h * 64;
    op[lane] = y0; op[lane + 32] = y1;
}

// ---------------- mini self-attention over M=64 tokens, one block per (b,h) ----------------
__global__ __launch_bounds__(256)
void attn_kernel(const float* __restrict__ qkv, float* __restrict__ otok)
{
    int bh = blockIdx.x; int b = bh >> 3, h = bh & 7;
    __shared__ float qs[64][68];
    __shared__ float ks[64][68];
    int tid = threadIdx.x;
    const float* base = qkv + (long long)b * 64 * 1536 + h * 64;

#pragma unroll
    for (int i = 0; i < 4; i++) {
        int idx = tid + i * 256;
        int m = idx >> 4, c4 = idx & 15;
        *(float4*)&qs[m][c4 * 4] = *(const float4*)&base[(long long)m * 1536 + c4 * 4];
        *(float4*)&ks[m][c4 * 4] = *(const float4*)&base[(long long)m * 1536 + 512 + c4 * 4];
    }
    __syncthreads();

    int tx = tid & 15, ty = tid >> 4;
    float dots[4][4];
#pragma unroll
    for (int i = 0; i < 4; i++)
#pragma unroll
        for (int j = 0; j < 4; j++) dots[i][j] = 0.f;
#pragma unroll
    for (int d = 0; d < 64; d += 4) {
        float4 ra[4], rb[4];
#pragma unroll
        for (int i = 0; i < 4; i++) ra[i] = *(float4*)&qs[ty * 4 + i][d];
#pragma unroll
        for (int j = 0; j < 4; j++) rb[j] = *(float4*)&ks[tx * 4 + j][d];
#pragma unroll
        for (int i = 0; i < 4; i++)
#pragma unroll
            for (int j = 0; j < 4; j++)
                dots[i][j] += ra[i].x * rb[j].x + ra[i].y * rb[j].y +
                              ra[i].z * rb[j].z + ra[i].w * rb[j].w;
    }
    __syncthreads();
#pragma unroll
    for (int i = 0; i < 4; i++)
#pragma unroll
        for (int j = 0; j < 4; j++)
            qs[ty * 4 + i][tx * 4 + j] = dots[i][j] * 0.125f;
#pragma unroll
    for (int i = 0; i < 4; i++) {
        int idx = tid + i * 256;
        int m = idx >> 4, c4 = idx & 15;
        *(float4*)&ks[m][c4 * 4] = *(const float4*)&base[(long long)m * 1536 + 1024 + c4 * 4];
    }
    __syncthreads();

    int wid = tid >> 5, lane = tid & 31;
#pragma unroll
    for (int r = 0; r < 8; r++) {
        int m = wid * 8 + r;
        float a0 = qs[m][lane], a1 = qs[m][lane + 32];
        float mx = fmaxf(a0, a1);
#pragma unroll
        for (int o = 16; o; o >>= 1) mx = fmaxf(mx, __shfl_xor_sync(0xffffffffu, mx, o));
        float e0 = __expf(a0 - mx), e1 = __expf(a1 - mx);
        float s = e0 + e1;
#pragma unroll
        for (int o = 16; o; o >>= 1) s += __shfl_xor_sync(0xffffffffu, s, o);
        float inv = 1.0f / s;
        qs[m][lane] = e0 * inv; qs[m][lane + 32] = e1 * inv;
    }
    __syncthreads();

    float acc[4][4];
#pragma unroll
    for (int i = 0; i < 4; i++)
#pragma unroll
        for (int j = 0; j < 4; j++) acc[i][j] = 0.f;
#pragma unroll 4
    for (int k = 0; k < 64; k++) {
        float rm[4];
#pragma unroll
        for (int i = 0; i < 4; i++) rm[i] = qs[ty * 4 + i][k];
        float4 rv = *(float4*)&ks[k][tx * 4];
#pragma unroll
        for (int i = 0; i < 4; i++) {
            acc[i][0] += rm[i] * rv.x; acc[i][1] += rm[i] * rv.y;
            acc[i][2] += rm[i] * rv.z; acc[i][3] += rm[i] * rv.w;
        }
    }
    float* op = otok + (long long)bh * 4096;
#pragma unroll
    for (int i = 0; i < 4; i++) {
        float4 v = {acc[i][0], acc[i][1], acc[i][2], acc[i][3]};
        *(float4*)&op[(ty * 4 + i) * 64 + tx * 4] = v;
    }
}

// ---------------- scatter: pre[b,n,h*64+d] = sum_m otok[b,h,m,d] * slice_w[b,h*64+m,n] ----------------
__global__ __launch_bounds__(256)
void scatter_kernel(const float* __restrict__ sw, const float* __restrict__ otok,
                    float* __restrict__ pre)
{
    int bh = blockIdx.y; int b = bh >> 3, h = bh & 7;
    int n0 = blockIdx.x * 64;
    __shared__ float sws[64][68];
    __shared__ float ots[64][64];
    int tid = threadIdx.x;

    const float* swb = sw + ((long long)b * 512 + h * 64) * NN;
#pragma unroll
    for (int i = 0; i < 4; i++) {
        int idx = tid + i * 256;
        int m = idx >> 4, c4 = idx & 15;
        *(float4*)&sws[m][c4 * 4] = *(const float4*)&swb[(long long)m * NN + n0 + c4 * 4];
        *(float4*)&ots[m][c4 * 4] = *(const float4*)&otok[(long long)bh * 4096 + m * 64 + c4 * 4];
    }
    __syncthreads();

    int tx = tid & 15, ty = tid >> 4;
    float acc[4][4];
#pragma unroll
    for (int i = 0; i < 4; i++)
#pragma unroll
        for (int j = 0; j < 4; j++) acc[i][j] = 0.f;
#pragma unroll 4
    for (int m = 0; m < 64; m++) {
        float rn[4];
#pragma unroll
        for (int i = 0; i < 4; i++) rn[i] = sws[m][ty * 4 + i];
        float4 rd = *(float4*)&ots[m][tx * 4];
#pragma unroll
        for (int i = 0; i < 4; i++) {
            acc[i][0] += rn[i] * rd.x; acc[i][1] += rn[i] * rd.y;
            acc[i][2] += rn[i] * rd.z; acc[i][3] += rn[i] * rd.w;
        }
    }
    float* pb = pre + (long long)b * NN * 512 + h * 64;
#pragma unroll
    for (int i = 0; i < 4; i++) {
        long long n = n0 + ty * 4 + i;
        float4 v = {acc[i][0], acc[i][1], acc[i][2], acc[i][3]};
        *(float4*)&pb[n * 512 + tx * 4] = v;
    }
}

// ---------------- launch ----------------
extern "C" void kernel_launch(void* const* d_in, const int* in_sizes, int n_in,
                              void* d_out, int out_size)
{
    (void)in_sizes; (void)n_in; (void)out_size;
    const float* x     = (const float*)d_in[0];
    const float* W_kv  = (const float*)d_in[1];
    const float* b_kv  = (const float*)d_in[2];
    const float* wtq   = (const float*)d_in[3];
    const float* W_mix = (const float*)d_in[4];
    const float* ln_g  = (const float*)d_in[5];
    const float* ln_b  = (const float*)d_in[6];
    const float* W_qkv = (const float*)d_in[7];
    const float* W_out = (const float*)d_in[8];
    const float* b_out = (const float*)d_in[9];
    float* out = (float*)d_out;

    float *kv, *scores, *mixed, *sumw, *part, *stok, *st, *qkv, *otok, *pre;
    cudaGetSymbolAddress((void**)&kv, g_kv);
    cudaGetSymbolAddress((void**)&scores, g_scores);
    cudaGetSymbolAddress((void**)&mixed, g_mixed);
    cudaGetSymbolAddress((void**)&sumw, g_sumw);
    cudaGetSymbolAddress((void**)&part, g_part);
    cudaGetSymbolAddress((void**)&stok, g_stok);
    cudaGetSymbolAddress((void**)&st, g_st);
    cudaGetSymbolAddress((void**)&qkv, g_qkv);
    cudaGetSymbolAddress((void**)&otok, g_otok);
    cudaGetSymbolAddress((void**)&pre, g_pre);

    // 1) kv = x @ W_kv + b_kv              [65536,1024] K=512  (tf32 mma)
    mma_gemm_kernel<<<dim3(1024 / 128, 65536 / 128, 1), 256>>>(
        x, W_kv, b_kv, kv, 1024, 512, 0, 0, 0);

    // 2) scores = wtq . xk                 per (b,h): [64,64] x [64,8192]
    scores_kernel<<<dim3(NN / 64, 64), 256>>>(kv, wtq, scores);

    // 3) mixed = W_mix @ scores            per b: [512,8192] K=512  (tf32 mma)
    mma_gemm_kernel<<<dim3(NN / 128, 512 / 128, BB), 256>>>(
        W_mix, scores, nullptr, mixed, NN, 512,
        0, (long long)512 * NN, (long long)512 * NN);

    // 4) softmax over m (in place -> slice_w)
    softmax_kernel<<<dim3(NN / 256, 64), 256>>>(mixed);

    // 4b) sumw over n
    sumw_kernel<<<4096, 256>>>(mixed, sumw);

    // 5) slice_tok = slice_w @ xv (deterministic split-K)
    stok_part_kernel<<<dim3(16, 64), 256>>>(mixed, kv, part);
    stok_reduce_kernel<<<64, 256>>>(part, stok);

    // 6) normalize + layernorm -> st[B,M,D]
    ln_kernel<<<512, 256>>>(stok, sumw, ln_g, ln_b, st);

    // 7) qkv = st @ W_qkv                  [512,1536] K=512 (SIMT; tiny)
    sgemm_kernel<<<dim3(1536 / 128, 512 / 128, 1), 256>>>(
        st, W_qkv, nullptr, qkv, 512, 1536, 512, 0, 0, 0);

    // 8) mini self-attention over M
    attn_kernel<<<64, 256>>>(qkv, otok);

    // 9) scatter: pre = otok^T applied through slice_w
    scatter_kernel<<<dim3(NN / 64, 64), 256>>>(mixed, otok, pre);

    // 10) out = pre @ W_out + b_out        [65536,512] K=512  (tf32 mma)
    mma_gemm_kernel<<<dim3(512 / 128, 65536 / 128, 1), 256>>>(
        pre, W_out, b_out, out, 512, 512, 0, 0, 0);
}

// round 7
// speedup vs baseline: 3.1458x; 1.4591x over previous
#include <cuda_runtime.h>
#include <cuda_fp16.h>
#include <cstdint>

// ---------------- constants ----------------
#define BB 8
#define NN 8192

// ---------------- device scratch (no allocs allowed; 256B-aligned for vector LD/ST) ----------------
__device__ __align__(256) float g_kv[67108864];        // [B,N,2D]  256MB
__device__ __align__(256) float g_mixed[33554432];     // [B*N, 512] n-major logits -> slice_w
__device__ __align__(256) float g_sumw[4096];          // [B,512]
__device__ __align__(256) float g_part[4194304];       // [64 bh][16 splits][64m*64d]
__device__ __align__(256) float g_partsum[65536];      // [64 bh][16 splits][64m]
__device__ __align__(256) float g_stok[262144];        // [B,H,M,HD]
__device__ __align__(256) float g_st[262144];          // [B,M,D]
__device__ __align__(256) float g_qkv[786432];         // [B*M, 1536]
__device__ __align__(256) float g_otok[262144];        // [B,H,M,HD]
__device__ __align__(256) __half g_WkvT[524288];       // [1024][512]
__device__ __align__(256) __half g_WqkvT[786432];      // [1536][512]
__device__ __align__(256) __half g_Wf[262144];         // [512 o][512 hd]
__device__ __align__(256) __half g_GT[2097152];        // [B][512 e][512 hm]

// ================= fp16 mma GEMM =================
__device__ __forceinline__ void mma_fp16(float* d, const uint32_t* a, const uint32_t* b) {
    asm volatile(
        "mma.sync.aligned.m16n8k16.row.col.f32.f16.f16.f32 "
        "{%0,%1,%2,%3}, {%4,%5,%6,%7}, {%8,%9}, {%0,%1,%2,%3};"
        : "+f"(d[0]), "+f"(d[1]), "+f"(d[2]), "+f"(d[3])
        : "r"(a[0]), "r"(a[1]), "r"(a[2]), "r"(a[3]), "r"(b[0]), "r"(b[1]));
}
__device__ __forceinline__ uint32_t h2u(__half2 h) { return *reinterpret_cast<uint32_t*>(&h); }

#define HSTR 24   // halfs per smem row (48B stride -> conflict-free frag LDS, 16B-aligned rows)

// C[M,N] = A[M,K](f32, lda) @ Bt[N,K](half)^T (+bias). M%128==0, N%128==0, K%16==0.
// 256 threads, 8 warps in 2x4, warp tile 64x32, k-chunk 16, double-buffered.
__global__ __launch_bounds__(256)
void hgemm_kernel(const float* __restrict__ A, const __half* __restrict__ Bt,
                  const float* __restrict__ bias, float* __restrict__ C,
                  int Nd, int Kd, int lda,
                  long long Abs, long long Bbs, long long Cbs)
{
    A  += blockIdx.z * Abs;
    Bt += blockIdx.z * Bbs;
    C  += blockIdx.z * Cbs;

    __shared__ __align__(16) __half As[2][128 * HSTR];
    __shared__ __align__(16) __half Bs[2][128 * HSTR];

    const int tid = threadIdx.x, lane = tid & 31, wid = tid >> 5;
    const int wm = wid & 1, wn = wid >> 1;
    const int g = lane >> 2, t = lane & 3;
    const int m0 = blockIdx.y * 128, n0 = blockIdx.x * 128;

    float acc[4][4][4];
#pragma unroll
    for (int i = 0; i < 4; i++)
#pragma unroll
        for (int j = 0; j < 4; j++)
#pragma unroll
            for (int r = 0; r < 4; r++) acc[i][j][r] = 0.f;

    const int lr = tid >> 1;            // 0..127 tile row (A) / tile n (B)
    const int lp = (tid & 1) * 8;       // 0 or 8 element offset

    const float*  Ap = A  + (long long)(m0 + lr) * lda + lp;
    const __half* Bp = Bt + (long long)(n0 + lr) * Kd + lp;

    float4 ra0, ra1; uint4 rbv;
    ra0 = *(const float4*)(Ap + 0);
    ra1 = *(const float4*)(Ap + 4);
    rbv = *(const uint4*)(Bp);
    {
        __half2 h0 = __floats2half2_rn(ra0.x, ra0.y);
        __half2 h1 = __floats2half2_rn(ra0.z, ra0.w);
        __half2 h2 = __floats2half2_rn(ra1.x, ra1.y);
        __half2 h3 = __floats2half2_rn(ra1.z, ra1.w);
        uint4 av = { h2u(h0), h2u(h1), h2u(h2), h2u(h3) };
        *(uint4*)&As[0][lr * HSTR + lp] = av;
        *(uint4*)&Bs[0][lr * HSTR + lp] = rbv;
    }
    __syncthreads();

    const int NK = Kd >> 4;
    for (int ck = 0; ck < NK; ck++) {
        const int buf = ck & 1;
        const bool more = (ck + 1) < NK;
        if (more) {
            ra0 = *(const float4*)(Ap + (ck + 1) * 16);
            ra1 = *(const float4*)(Ap + (ck + 1) * 16 + 4);
            rbv = *(const uint4*)(Bp + (ck + 1) * 16);
        }
        uint32_t af[4][4], bf[4][2];
#pragma unroll
        for (int i = 0; i < 4; i++) {
            const __half* base = &As[buf][(wm * 64 + i * 16 + g) * HSTR + 2 * t];
            af[i][0] = *(const uint32_t*)(base);
            af[i][1] = *(const uint32_t*)(base + 8 * HSTR);
            af[i][2] = *(const uint32_t*)(base + 8);
            af[i][3] = *(const uint32_t*)(base + 8 * HSTR + 8);
        }
#pragma unroll
        for (int j = 0; j < 4; j++) {
            const __half* base = &Bs[buf][(wn * 32 + j * 8 + g) * HSTR + 2 * t];
            bf[j][0] = *(const uint32_t*)(base);
            bf[j][1] = *(const uint32_t*)(base + 8);
        }
#pragma unroll
        for (int i = 0; i < 4; i++)
#pragma unroll
            for (int j = 0; j < 4; j++)
                mma_fp16(acc[i][j], af[i], bf[j]);

        if (more) {
            const int nb = buf ^ 1;
            __half2 h0 = __floats2half2_rn(ra0.x, ra0.y);
            __half2 h1 = __floats2half2_rn(ra0.z, ra0.w);
            __half2 h2 = __floats2half2_rn(ra1.x, ra1.y);
            __half2 h3 = __floats2half2_rn(ra1.z, ra1.w);
            uint4 av = { h2u(h0), h2u(h1), h2u(h2), h2u(h3) };
            *(uint4*)&As[nb][lr * HSTR + lp] = av;
            *(uint4*)&Bs[nb][lr * HSTR + lp] = rbv;
            __syncthreads();
        }
    }

    // epilogue
#pragma unroll
    for (int i = 0; i < 4; i++) {
#pragma unroll
        for (int j = 0; j < 4; j++) {
            int col = n0 + wn * 32 + j * 8 + t * 2;
            float bx = 0.f, by = 0.f;
            if (bias) { bx = bias[col]; by = bias[col + 1]; }
            long long row0 = m0 + wm * 64 + i * 16 + g;
            float2 v0 = { acc[i][j][0] + bx, acc[i][j][1] + by };
            float2 v1 = { acc[i][j][2] + bx, acc[i][j][3] + by };
            *(float2*)&C[row0 * Nd + col] = v0;
            *(float2*)&C[(row0 + 8) * Nd + col] = v1;
        }
    }
}

// ---------------- prep: Wt[n][k] = (half)W[k][n], W is [512][Ncols] ----------------
__global__ __launch_bounds__(256)
void transpose_half_kernel(const float* __restrict__ W, __half* __restrict__ Wt, int Ncols)
{
    __shared__ float tile[32][33];
    int n0 = blockIdx.x * 32, k0 = blockIdx.y * 32;
    int tx = threadIdx.x & 31, ty = threadIdx.x >> 5;   // 8 row-steps
#pragma unroll
    for (int r = ty; r < 32; r += 8)
        tile[r][tx] = W[(long long)(k0 + r) * Ncols + n0 + tx];
    __syncthreads();
#pragma unroll
    for (int r = ty; r < 32; r += 8)
        Wt[(long long)(n0 + r) * 512 + k0 + tx] = __float2half_rn(tile[tx][r]);
}

// ---------------- prep: Wf[o][h*64+d] = sum_m W_mix[o,h*64+m] * wtq[h,m,d] ----------------
__global__ __launch_bounds__(256)
void wf_kernel(const float* __restrict__ W_mix, const float* __restrict__ wtq,
               __half* __restrict__ Wf)
{
    int h = blockIdx.x & 7, o0 = (blockIdx.x >> 3) * 64;
    __shared__ float wm[64][68];   // [o][m]  (stride 68 floats = 272B, 16B-aligned rows)
    __shared__ float wt[64][68];   // [m][d]
    int tid = threadIdx.x;
#pragma unroll
    for (int i = 0; i < 16; i++) {
        int idx = tid + i * 256;
        int r = idx >> 6, c = idx & 63;
        wm[r][c] = W_mix[(long long)(o0 + r) * 512 + h * 64 + c];
        wt[r][c] = wtq[(long long)h * 4096 + r * 64 + c];
    }
    __syncthreads();
    int tx = tid & 15, ty = tid >> 4;   // tx->d4, ty->o4
    float acc[4][4];
#pragma unroll
    for (int i = 0; i < 4; i++)
#pragma unroll
        for (int j = 0; j < 4; j++) acc[i][j] = 0.f;
    for (int m = 0; m < 64; m++) {
        float ro[4];
#pragma unroll
        for (int i = 0; i < 4; i++) ro[i] = wm[ty * 4 + i][m];
        float4 rd = *(float4*)&wt[m][tx * 4];
#pragma unroll
        for (int i = 0; i < 4; i++) {
            acc[i][0] += ro[i] * rd.x; acc[i][1] += ro[i] * rd.y;
            acc[i][2] += ro[i] * rd.z; acc[i][3] += ro[i] * rd.w;
        }
    }
#pragma unroll
    for (int i = 0; i < 4; i++)
#pragma unroll
        for (int j = 0; j < 4; j++)
            Wf[(long long)(o0 + ty * 4 + i) * 512 + h * 64 + tx * 4 + j] =
                __float2half_rn(acc[i][j]);
}

// ---------------- prep: GT[b][e][h*64+m] = sum_d otok[b,h,m,d] * W_out[h*64+d, e] ----------------
__global__ __launch_bounds__(256)
void gt_kernel(const float* __restrict__ otok, const float* __restrict__ W_out,
               __half* __restrict__ GT)
{
    int bh = blockIdx.y; int b = bh >> 3, h = bh & 7;
    int e0 = blockIdx.x * 64;
    __shared__ float ot[64][68];   // [m][d]
    __shared__ float wo[64][68];   // [d][e]
    int tid = threadIdx.x;
#pragma unroll
    for (int i = 0; i < 16; i++) {
        int idx = tid + i * 256;
        int r = idx >> 6, c = idx & 63;
        ot[r][c] = otok[(long long)bh * 4096 + r * 64 + c];
        wo[r][c] = W_out[(long long)(h * 64 + r) * 512 + e0 + c];
    }
    __syncthreads();
    int tx = tid & 15, ty = tid >> 4;   // tx->m4, ty->e4
    float acc[4][4];
#pragma unroll
    for (int i = 0; i < 4; i++)
#pragma unroll
        for (int j = 0; j < 4; j++) acc[i][j] = 0.f;
    for (int d = 0; d < 64; d++) {
        float re[4], rm[4];
#pragma unroll
        for (int i = 0; i < 4; i++) re[i] = wo[d][ty * 4 + i];
#pragma unroll
        for (int j = 0; j < 4; j++) rm[j] = ot[tx * 4 + j][d];
#pragma unroll
        for (int i = 0; i < 4; i++)
#pragma unroll
            for (int j = 0; j < 4; j++) acc[i][j] += re[i] * rm[j];
    }
#pragma unroll
    for (int i = 0; i < 4; i++)
#pragma unroll
        for (int j = 0; j < 4; j++)
            GT[((long long)b * 512 + e0 + ty * 4 + i) * 512 + h * 64 + tx * 4 + j] =
                __float2half_rn(acc[i][j]);
}

// ---------------- softmax over 64 contiguous (warp per group) ----------------
__global__ __launch_bounds__(256)
void softmax64_kernel(float* __restrict__ sw)
{
    int wid = threadIdx.x >> 5, lane = threadIdx.x & 31;
    long long grp = (long long)blockIdx.x * 8 + wid;    // bn*8 + h
    float* p = sw + grp * 64;
    float2 v = *(float2*)(p + lane * 2);
    float mx = fmaxf(v.x, v.y);
#pragma unroll
    for (int o = 16; o; o >>= 1) mx = fmaxf(mx, __shfl_xor_sync(0xffffffffu, mx, o));
    float e0 = __expf(v.x - mx), e1 = __expf(v.y - mx);
    float s = e0 + e1;
#pragma unroll
    for (int o = 16; o; o >>= 1) s += __shfl_xor_sync(0xffffffffu, s, o);
    float inv = 1.0f / s;
    *(float2*)(p + lane * 2) = make_float2(e0 * inv, e1 * inv);
}

// ---------------- slice_tok partials + sumw (split-K over n) ----------------
// part[bh][sp][m][d] = sum_{n in sp} sw[b,n,h*64+m]*xv[b,n,h*64+d]; partsum = sum sw
__global__ __launch_bounds__(256)
void stok_part_kernel(const float* __restrict__ sw, const float* __restrict__ kv,
                      float* __restrict__ part, float* __restrict__ partsum)
{
    int bh = blockIdx.y; int b = bh >> 3, h = bh & 7;
    int split = blockIdx.x;
    __shared__ float sws[64][68];   // [n][m]
    __shared__ float xvs[64][68];   // [n][d]
    int tid = threadIdx.x, tx = tid & 15, ty = tid >> 4;

    float acc[4][4], ssum[4];
#pragma unroll
    for (int i = 0; i < 4; i++) {
        ssum[i] = 0.f;
#pragma unroll
        for (int j = 0; j < 4; j++) acc[i][j] = 0.f;
    }
    const float* swb = sw + (long long)b * NN * 512 + h * 64;
    const float* xvb = kv + (long long)b * NN * 1024 + 512 + h * 64;

    for (int c = 0; c < 8; c++) {
        int n0 = split * 512 + c * 64;
#pragma unroll
        for (int i = 0; i < 4; i++) {
            int idx = tid + i * 256;
            int n = idx >> 4, c4 = idx & 15;
            *(float4*)&sws[n][c4 * 4] = *(const float4*)&swb[(long long)(n0 + n) * 512 + c4 * 4];
            *(float4*)&xvs[n][c4 * 4] = *(const float4*)&xvb[(long long)(n0 + n) * 1024 + c4 * 4];
        }
        __syncthreads();
#pragma unroll 4
        for (int n = 0; n < 64; n++) {
            float4 rm = *(float4*)&sws[n][ty * 4];
            float4 rd = *(float4*)&xvs[n][tx * 4];
            acc[0][0] += rm.x * rd.x; acc[0][1] += rm.x * rd.y;
            acc[0][2] += rm.x * rd.z; acc[0][3] += rm.x * rd.w;
            acc[1][0] += rm.y * rd.x; acc[1][1] += rm.y * rd.y;
            acc[1][2] += rm.y * rd.z; acc[1][3] += rm.y * rd.w;
            acc[2][0] += rm.z * rd.x; acc[2][1] += rm.z * rd.y;
            acc[2][2] += rm.z * rd.z; acc[2][3] += rm.z * rd.w;
            acc[3][0] += rm.w * rd.x; acc[3][1] += rm.w * rd.y;
            acc[3][2] += rm.w * rd.z; acc[3][3] += rm.w * rd.w;
            ssum[0] += rm.x; ssum[1] += rm.y; ssum[2] += rm.z; ssum[3] += rm.w;
        }
        __syncthreads();
    }
    float* pp = part + ((long long)bh * 16 + split) * 4096;
#pragma unroll
    for (int i = 0; i < 4; i++) {
        float4 v = {acc[i][0], acc[i][1], acc[i][2], acc[i][3]};
        *(float4*)&pp[(ty * 4 + i) * 64 + tx * 4] = v;
    }
    if (tx == 0) {
        float* ps = partsum + ((long long)bh * 16 + split) * 64;
#pragma unroll
        for (int i = 0; i < 4; i++) ps[ty * 4 + i] = ssum[i];
    }
}

__global__ __launch_bounds__(256)
void stok_reduce_kernel(const float* __restrict__ part, const float* __restrict__ partsum,
                        float* __restrict__ stok, float* __restrict__ sumw)
{
    int bh = blockIdx.x;
    for (int i = threadIdx.x; i < 4096; i += 256) {
        float s = 0.f;
#pragma unroll
        for (int sp = 0; sp < 16; sp++) s += part[((long long)bh * 16 + sp) * 4096 + i];
        stok[(long long)bh * 4096 + i] = s;
    }
    if (threadIdx.x < 64) {
        float s = 0.f;
#pragma unroll
        for (int sp = 0; sp < 16; sp++) s += partsum[((long long)bh * 16 + sp) * 64 + threadIdx.x];
        sumw[bh * 64 + threadIdx.x] = s;
    }
}

// ---------------- normalize by sumw + layernorm -> st[b,m,h*64+d] ----------------
__global__ __launch_bounds__(256)
void ln_kernel(const float* __restrict__ stok, const float* __restrict__ sumw,
               const float* __restrict__ gg, const float* __restrict__ bta,
               float* __restrict__ st)
{
    int warp = (blockIdx.x * blockDim.x + threadIdx.x) >> 5;   // b*512 + h*64 + m
    int lane = threadIdx.x & 31;
    int m = warp & 63, h = (warp >> 6) & 7, b = warp >> 9;

    float inv = 1.0f / (sumw[warp] + 1e-5f);
    const float* sp = stok + (long long)warp * 64;
    float x0 = sp[lane] * inv, x1 = sp[lane + 32] * inv;
    float s = x0 + x1;
#pragma unroll
    for (int o = 16; o; o >>= 1) s += __shfl_xor_sync(0xffffffffu, s, o);
    float mu = s * (1.0f / 64.0f);
    float d0 = x0 - mu, d1 = x1 - mu;
    float vs = d0 * d0 + d1 * d1;
#pragma unroll
    for (int o = 16; o; o >>= 1) vs += __shfl_xor_sync(0xffffffffu, vs, o);
    float rstd = rsqrtf(vs * (1.0f / 64.0f) + 1e-5f);
    float y0 = d0 * rstd * gg[lane] + bta[lane];
    float y1 = d1 * rstd * gg[lane + 32] + bta[lane + 32];
    float* op = st + ((long long)(b * 64 + m)) * 512 + h * 64;
    op[lane] = y0; op[lane + 32] = y1;
}

// ---------------- mini self-attention over M=64 tokens, one block per (b,h) ----------------
__global__ __launch_bounds__(256)
void attn_kernel(const float* __restrict__ qkv, float* __restrict__ otok)
{
    int bh = blockIdx.x; int b = bh >> 3, h = bh & 7;
    __shared__ float qs[64][68];
    __shared__ float ks[64][68];
    int tid = threadIdx.x;
    const float* base = qkv + (long long)b * 64 * 1536 + h * 64;

#pragma unroll
    for (int i = 0; i < 4; i++) {
        int idx = tid + i * 256;
        int m = idx >> 4, c4 = idx & 15;
        *(float4*)&qs[m][c4 * 4] = *(const float4*)&base[(long long)m * 1536 + c4 * 4];
        *(float4*)&ks[m][c4 * 4] = *(const float4*)&base[(long long)m * 1536 + 512 + c4 * 4];
    }
    __syncthreads();

    int tx = tid & 15, ty = tid >> 4;
    float dots[4][4];
#pragma unroll
    for (int i = 0; i < 4; i++)
#pragma unroll
        for (int j = 0; j < 4; j++) dots[i][j] = 0.f;
#pragma unroll
    for (int d = 0; d < 64; d += 4) {
        float4 ra[4], rb[4];
#pragma unroll
        for (int i = 0; i < 4; i++) ra[i] = *(float4*)&qs[ty * 4 + i][d];
#pragma unroll
        for (int j = 0; j < 4; j++) rb[j] = *(float4*)&ks[tx * 4 + j][d];
#pragma unroll
        for (int i = 0; i < 4; i++)
#pragma unroll
            for (int j = 0; j < 4; j++)
                dots[i][j] += ra[i].x * rb[j].x + ra[i].y * rb[j].y +
                              ra[i].z * rb[j].z + ra[i].w * rb[j].w;
    }
    __syncthreads();
#pragma unroll
    for (int i = 0; i < 4; i++)
#pragma unroll
        for (int j = 0; j < 4; j++)
            qs[ty * 4 + i][tx * 4 + j] = dots[i][j] * 0.125f;
#pragma unroll
    for (int i = 0; i < 4; i++) {
        int idx = tid + i * 256;
        int m = idx >> 4, c4 = idx & 15;
        *(float4*)&ks[m][c4 * 4] = *(const float4*)&base[(long long)m * 1536 + 1024 + c4 * 4];
    }
    __syncthreads();

    int wid = tid >> 5, lane = tid & 31;
#pragma unroll
    for (int r = 0; r < 8; r++) {
        int m = wid * 8 + r;
        float a0 = qs[m][lane], a1 = qs[m][lane + 32];
        float mx = fmaxf(a0, a1);
#pragma unroll
        for (int o = 16; o; o >>= 1) mx = fmaxf(mx, __shfl_xor_sync(0xffffffffu, mx, o));
        float e0 = __expf(a0 - mx), e1 = __expf(a1 - mx);
        float s = e0 + e1;
#pragma unroll
        for (int o = 16; o; o >>= 1) s += __shfl_xor_sync(0xffffffffu, s, o);
        float inv = 1.0f / s;
        qs[m][lane] = e0 * inv; qs[m][lane + 32] = e1 * inv;
    }
    __syncthreads();

    float acc[4][4];
#pragma unroll
    for (int i = 0; i < 4; i++)
#pragma unroll
        for (int j = 0; j < 4; j++) acc[i][j] = 0.f;
#pragma unroll 4
    for (int k = 0; k < 64; k++) {
        float rm[4];
#pragma unroll
        for (int i = 0; i < 4; i++) rm[i] = qs[ty * 4 + i][k];
        float4 rv = *(float4*)&ks[k][tx * 4];
#pragma unroll
        for (int i = 0; i < 4; i++) {
            acc[i][0] += rm[i] * rv.x; acc[i][1] += rm[i] * rv.y;
            acc[i][2] += rm[i] * rv.z; acc[i][3] += rm[i] * rv.w;
        }
    }
    float* op = otok + (long long)bh * 4096;
#pragma unroll
    for (int i = 0; i < 4; i++) {
        float4 v = {acc[i][0], acc[i][1], acc[i][2], acc[i][3]};
        *(float4*)&op[(ty * 4 + i) * 64 + tx * 4] = v;
    }
}

// ---------------- launch ----------------
extern "C" void kernel_launch(void* const* d_in, const int* in_sizes, int n_in,
                              void* d_out, int out_size)
{
    (void)in_sizes; (void)n_in; (void)out_size;
    const float* x     = (const float*)d_in[0];
    const float* W_kv  = (const float*)d_in[1];
    const float* b_kv  = (const float*)d_in[2];
    const float* wtq   = (const float*)d_in[3];
    const float* W_mix = (const float*)d_in[4];
    const float* ln_g  = (const float*)d_in[5];
    const float* ln_b  = (const float*)d_in[6];
    const float* W_qkv = (const float*)d_in[7];
    const float* W_out = (const float*)d_in[8];
    const float* b_out = (const float*)d_in[9];
    float* out = (float*)d_out;

    float *kv, *mixed, *sumw, *part, *partsum, *stok, *st, *qkv, *otok;
    __half *WkvT, *WqkvT, *Wf, *GT;
    cudaGetSymbolAddress((void**)&kv, g_kv);
    cudaGetSymbolAddress((void**)&mixed, g_mixed);
    cudaGetSymbolAddress((void**)&sumw, g_sumw);
    cudaGetSymbolAddress((void**)&part, g_part);
    cudaGetSymbolAddress((void**)&partsum, g_partsum);
    cudaGetSymbolAddress((void**)&stok, g_stok);
    cudaGetSymbolAddress((void**)&st, g_st);
    cudaGetSymbolAddress((void**)&qkv, g_qkv);
    cudaGetSymbolAddress((void**)&otok, g_otok);
    cudaGetSymbolAddress((void**)&WkvT, g_WkvT);
    cudaGetSymbolAddress((void**)&WqkvT, g_WqkvT);
    cudaGetSymbolAddress((void**)&Wf, g_Wf);
    cudaGetSymbolAddress((void**)&GT, g_GT);

    // prep: transposed half weights + folded Wf
    transpose_half_kernel<<<dim3(1024 / 32, 512 / 32), 256>>>(W_kv, WkvT, 1024);
    transpose_half_kernel<<<dim3(1536 / 32, 512 / 32), 256>>>(W_qkv, WqkvT, 1536);
    wf_kernel<<<64, 256>>>(W_mix, wtq, Wf);

    // 1) kv = x @ W_kv + b_kv      [65536,1024] K=512
    hgemm_kernel<<<dim3(1024 / 128, 65536 / 128, 1), 256>>>(
        x, WkvT, b_kv, kv, 1024, 512, 512, 0, 0, 0);

    // 2) mixed = xk @ Wf^T         [65536,512] K=512 (A = kv first half, lda=1024)
    hgemm_kernel<<<dim3(512 / 128, 65536 / 128, 1), 256>>>(
        kv, Wf, nullptr, mixed, 512, 512, 1024, 0, 0, 0);

    // 3) softmax over m (64 contiguous per (b,n,h)) -> slice_w in place
    softmax64_kernel<<<65536, 256>>>(mixed);

    // 4) slice_tok + sumw (deterministic split-K)
    stok_part_kernel<<<dim3(16, 64), 256>>>(mixed, kv, part, partsum);
    stok_reduce_kernel<<<64, 256>>>(part, partsum, stok, sumw);

    // 5) normalize + layernorm -> st[B,M,D]
    ln_kernel<<<512, 256>>>(stok, sumw, ln_g, ln_b, st);

    // 6) qkv = st @ W_qkv          [512,1536] K=512
    hgemm_kernel<<<dim3(1536 / 128, 512 / 128, 1), 256>>>(
        st, WqkvT, nullptr, qkv, 1536, 512, 512, 0, 0, 0);

    // 7) mini self-attention over M
    attn_kernel<<<64, 256>>>(qkv, otok);

    // 8) GT[b] = (otok . W_out) folded scatter weights
    gt_kernel<<<dim3(8, 64), 256>>>(otok, W_out, GT);

    // 9) out[b] = sw[b] @ G[b] + b_out   per-b: [8192,512] K=512
    hgemm_kernel<<<dim3(512 / 128, 8192 / 128, BB), 256>>>(
        mixed, GT, b_out, out, 512, 512, 512,
        (long long)8192 * 512, (long long)512 * 512, (long long)8192 * 512);
}